// round 16
// baseline (speedup 1.0000x reference)
#include <cuda_runtime.h>
#include <cstdint>

namespace {
constexpr int NS    = 512;
constexpr int MPTS  = 8192;
constexpr int HW    = 16384;
constexpr int HW4   = 4096;
constexpr int BLOCK = 256;
}

__device__ __forceinline__ float frcp(float x)  { float r; asm("rcp.approx.f32 %0,%1;"  : "=f"(r) : "f"(x)); return r; }
__device__ __forceinline__ float fsqrt(float x) { float r; asm("sqrt.approx.f32 %0,%1;" : "=f"(r) : "f"(x)); return r; }

__global__ void __launch_bounds__(BLOCK, 5) score_kernel(
    const int*   __restrict__ obj_id,
    const float* __restrict__ camK,
    const float* __restrict__ Rg_all,
    const float* __restrict__ tg_all,
    const float* __restrict__ Rp_all,
    const float* __restrict__ tp_all,
    const float* __restrict__ coord,    // [N,3,H,W]
    const void*  __restrict__ mask,     // [N,1,H,W]
    const float* __restrict__ mesh,     // [NOBJ,M,3]
    const float* __restrict__ diam,
    float*       __restrict__ out)      // [5*N]: re|te|ad|pj|pv
{
    const int tid  = threadIdx.x;
    const int lane = tid & 31;
    const int b    = blockIdx.x;
    const bool is_pv = (b < NS);
    const int n    = is_pv ? b : b - NS;

    __shared__ float s1[256];
    __shared__ float s2[256];
    __shared__ int   smode;

    // ---- mask dtype detection (warp 0 reads first 512B; L2-broadcast) ----
    if (tid < 32) {
        const unsigned* mw = (const unsigned*)mask;
        unsigned f = 0, o = 0;
#pragma unroll
        for (int k = 0; k < 4; k++) {
            unsigned w = __ldg(mw + lane + 32 * k);
            if (w == 0x3F800000u) f = 1;
            else if (w > 1u) o = 1;
        }
        f = __any_sync(0xFFFFFFFFu, f);
        o = __any_sync(0xFFFFFFFFu, o);
        if (lane == 0) smode = f ? 0 : (o ? 2 : 1);   // 0=f32 1=i32 2=packed u8
    }

    // ---- per-sample constants (broadcast loads, cached) ----
    float Rp[9], Rg[9], tp[3], tg[3];
#pragma unroll
    for (int i = 0; i < 9; i++) { Rp[i] = Rp_all[n * 9 + i]; Rg[i] = Rg_all[n * 9 + i]; }
#pragma unroll
    for (int i = 0; i < 3; i++) { tp[i] = tp_all[n * 3 + i]; tg[i] = tg_all[n * 3 + i]; }
    const float fx = camK[n * 9 + 0];
    const float fy = camK[n * 9 + 4];

    __syncthreads();
    const int mode = smode;

    if (is_pv) {
        // ---- PROJ-visible over ROI pixels ----
        const float4* x4 = (const float4*)(coord + (size_t)n * 3 * HW);
        const float4* y4 = x4 + HW4;
        const float4* z4 = y4 + HW4;
        float sum = 0.f, cnt = 0.f;

        for (int i = tid; i < HW4; i += BLOCK) {
            float4 X = x4[i], Y = y4[i], Z = z4[i];
            float mv[4];
            if (mode == 0) {
                float4 mm = ((const float4*)mask)[(size_t)n * HW4 + i];
                mv[0] = mm.x; mv[1] = mm.y; mv[2] = mm.z; mv[3] = mm.w;
            } else if (mode == 1) {
                int4 mm = ((const int4*)mask)[(size_t)n * HW4 + i];
                mv[0] = (float)mm.x; mv[1] = (float)mm.y;
                mv[2] = (float)mm.z; mv[3] = (float)mm.w;
            } else {
                unsigned w = ((const unsigned*)mask)[(size_t)n * HW4 + i];
                mv[0] = (float)(w & 0xFFu);
                mv[1] = (float)((w >> 8) & 0xFFu);
                mv[2] = (float)((w >> 16) & 0xFFu);
                mv[3] = (float)(w >> 24);
            }
            const float xs[4] = {X.x, X.y, X.z, X.w};
            const float ys[4] = {Y.x, Y.y, Y.z, Y.w};
            const float zs[4] = {Z.x, Z.y, Z.z, Z.w};
#pragma unroll
            for (int k = 0; k < 4; k++) {
                const float v0 = xs[k], v1 = ys[k], v2 = zs[k];
                float p0 = fmaf(Rp[0], v0, fmaf(Rp[1], v1, fmaf(Rp[2], v2, tp[0])));
                float p1 = fmaf(Rp[3], v0, fmaf(Rp[4], v1, fmaf(Rp[5], v2, tp[1])));
                float p2 = fmaf(Rp[6], v0, fmaf(Rp[7], v1, fmaf(Rp[8], v2, tp[2])));
                float g0 = fmaf(Rg[0], v0, fmaf(Rg[1], v1, fmaf(Rg[2], v2, tg[0])));
                float g1 = fmaf(Rg[3], v0, fmaf(Rg[4], v1, fmaf(Rg[5], v2, tg[1])));
                float g2 = fmaf(Rg[6], v0, fmaf(Rg[7], v1, fmaf(Rg[8], v2, tg[2])));
                float rp = frcp(p2);
                float rg = frcp(g2);
                float a0 = fmaf(p0, rp, -(g0 * rg));
                float a1 = fmaf(p1, rp, -(g1 * rg));
                float du = fx * a0;
                float dv = fy * a1;
                float d  = fsqrt(fmaf(du, du, dv * dv));
                sum = fmaf(d, mv[k], sum);
                cnt += mv[k];
            }
        }
        s1[tid] = sum; s2[tid] = cnt;
        __syncthreads();
        for (int s = 128; s > 0; s >>= 1) {
            if (tid < s) { s1[tid] += s1[tid + s]; s2[tid] += s2[tid + s]; }
            __syncthreads();
        }
        if (tid == 0) out[4 * NS + n] = s1[0] / fmaxf(s2[0], 1.0f);
    } else {
        // ---- ADD + PROJ over mesh points (+ RE/TE) ----
        const int obj = obj_id[n];
        const float* mp = mesh + (size_t)obj * MPTS * 3;
        float adsum = 0.f, pjsum = 0.f;

        for (int m = tid; m < MPTS; m += BLOCK) {
            const float v0 = __ldg(mp + m * 3 + 0);
            const float v1 = __ldg(mp + m * 3 + 1);
            const float v2 = __ldg(mp + m * 3 + 2);
            float p0 = fmaf(Rp[0], v0, fmaf(Rp[1], v1, fmaf(Rp[2], v2, tp[0])));
            float p1 = fmaf(Rp[3], v0, fmaf(Rp[4], v1, fmaf(Rp[5], v2, tp[1])));
            float p2 = fmaf(Rp[6], v0, fmaf(Rp[7], v1, fmaf(Rp[8], v2, tp[2])));
            float g0 = fmaf(Rg[0], v0, fmaf(Rg[1], v1, fmaf(Rg[2], v2, tg[0])));
            float g1 = fmaf(Rg[3], v0, fmaf(Rg[4], v1, fmaf(Rg[5], v2, tg[1])));
            float g2 = fmaf(Rg[6], v0, fmaf(Rg[7], v1, fmaf(Rg[8], v2, tg[2])));
            // ADD: |(pred - gt) transformed| == |xp - xg|
            float e0 = p0 - g0, e1 = p1 - g1, e2 = p2 - g2;
            adsum += fsqrt(fmaf(e0, e0, fmaf(e1, e1, e2 * e2)));
            // PROJ
            float rp = frcp(p2);
            float rg = frcp(g2);
            float a0 = fmaf(p0, rp, -(g0 * rg));
            float a1 = fmaf(p1, rp, -(g1 * rg));
            float du = fx * a0;
            float dv = fy * a1;
            pjsum += fsqrt(fmaf(du, du, dv * dv));
        }
        s1[tid] = adsum; s2[tid] = pjsum;
        __syncthreads();
        for (int s = 128; s > 0; s >>= 1) {
            if (tid < s) { s1[tid] += s1[tid + s]; s2[tid] += s2[tid + s]; }
            __syncthreads();
        }
        if (tid == 0) {
            const float invM = 1.0f / (float)MPTS;
            out[2 * NS + n] = (s1[0] * invM) / __ldg(diam + obj);
            out[3 * NS + n] = s2[0] * invM;
            float tr = 0.f;
#pragma unroll
            for (int i = 0; i < 9; i++) tr = fmaf(Rp[i], Rg[i], tr);
            tr = fminf(fmaxf(tr, -1.0f), 3.0f);
            out[n] = acosf((tr - 1.0f) * 0.5f) * 57.29577951308232f;
            const float d0 = tp[0] - tg[0], d1 = tp[1] - tg[1], d2 = tp[2] - tg[2];
            out[NS + n] = sqrtf(fmaf(d0, d0, fmaf(d1, d1, d2 * d2))) * 100.0f;
        }
    }
}

extern "C" void kernel_launch(void* const* d_in, const int* in_sizes, int n_in,
                              void* d_out, int out_size) {
    (void)in_sizes; (void)n_in; (void)out_size;
    const int*   obj_id = (const int*)  d_in[0];
    const float* camK   = (const float*)d_in[1];
    const float* gtR    = (const float*)d_in[2];
    const float* gtT    = (const float*)d_in[3];
    const float* prR    = (const float*)d_in[4];
    const float* prT    = (const float*)d_in[5];
    const float* coord  = (const float*)d_in[6];
    const void*  mask   =               d_in[7];
    const float* mesh   = (const float*)d_in[8];
    const float* diam   = (const float*)d_in[9];
    float* out = (float*)d_out;

    score_kernel<<<2 * NS, BLOCK>>>(obj_id, camK, gtR, gtT, prR, prT,
                                    coord, mask, mesh, diam, out);
}

// round 17
// speedup vs baseline: 1.2174x; 1.2174x over previous
#include <cuda_runtime.h>
#include <cstdint>

namespace {
constexpr int NS    = 512;
constexpr int MPTS  = 8192;
constexpr int HW    = 16384;
constexpr int HW4   = 4096;
constexpr int BLOCK = 256;
}

__device__ __forceinline__ float frcp(float x)  { float r; asm("rcp.approx.f32 %0,%1;"  : "=f"(r) : "f"(x)); return r; }
__device__ __forceinline__ float fsqrt(float x) { float r; asm("sqrt.approx.f32 %0,%1;" : "=f"(r) : "f"(x)); return r; }

__global__ void __launch_bounds__(BLOCK) score_kernel(
    const int*   __restrict__ obj_id,
    const float* __restrict__ camK,
    const float* __restrict__ Rg_all,
    const float* __restrict__ tg_all,
    const float* __restrict__ Rp_all,
    const float* __restrict__ tp_all,
    const float* __restrict__ coord,    // [N,3,H,W]
    const void*  __restrict__ mask,     // [N,1,H,W]
    const float* __restrict__ mesh,     // [NOBJ,M,3]
    const float* __restrict__ diam,
    float*       __restrict__ out)      // [5*N]: re|te|ad|pj|pv
{
    const int tid  = threadIdx.x;
    const int lane = tid & 31;
    const int b    = blockIdx.x;
    const bool is_pv = (b < NS);
    const int n    = is_pv ? b : b - NS;

    __shared__ float s1[256];
    __shared__ float s2[256];

    // ---- per-sample constants (broadcast loads, cached) ----
    float Rp[9], Rg[9], tp[3], tg[3];
#pragma unroll
    for (int i = 0; i < 9; i++) { Rp[i] = Rp_all[n * 9 + i]; Rg[i] = Rg_all[n * 9 + i]; }
#pragma unroll
    for (int i = 0; i < 3; i++) { tp[i] = tp_all[n * 3 + i]; tg[i] = tg_all[n * 3 + i]; }
    const float fx = camK[n * 9 + 0];
    const float fy = camK[n * 9 + 4];

    if (is_pv) {
        // ---- mask dtype detection: per-warp, barrier-free (same 512B, L2-broadcast)
        // 0 = float32, 1 = int32, 2 = packed uint8 (numpy bool)
        int mode;
        {
            const unsigned* mw = (const unsigned*)mask;
            unsigned fdet = 0, odet = 0;
#pragma unroll
            for (int k = 0; k < 4; k++) {
                unsigned w = __ldg(mw + lane + 32 * k);
                if (w == 0x3F800000u) fdet = 1;
                else if (w > 1u) odet = 1;
            }
            fdet = __any_sync(0xFFFFFFFFu, fdet);
            odet = __any_sync(0xFFFFFFFFu, odet);
            mode = fdet ? 0 : (odet ? 2 : 1);
        }

        // ---- PROJ-visible over ROI pixels ----
        const float4* x4 = (const float4*)(coord + (size_t)n * 3 * HW);
        const float4* y4 = x4 + HW4;
        const float4* z4 = y4 + HW4;
        float sum = 0.f, cnt = 0.f;

        for (int i = tid; i < HW4; i += BLOCK) {
            float4 X = x4[i], Y = y4[i], Z = z4[i];
            float mv[4];
            if (mode == 0) {
                float4 mm = ((const float4*)mask)[(size_t)n * HW4 + i];
                mv[0] = mm.x; mv[1] = mm.y; mv[2] = mm.z; mv[3] = mm.w;
            } else if (mode == 1) {
                int4 mm = ((const int4*)mask)[(size_t)n * HW4 + i];
                mv[0] = (float)mm.x; mv[1] = (float)mm.y;
                mv[2] = (float)mm.z; mv[3] = (float)mm.w;
            } else {
                unsigned w = ((const unsigned*)mask)[(size_t)n * HW4 + i];
                mv[0] = (float)(w & 0xFFu);
                mv[1] = (float)((w >> 8) & 0xFFu);
                mv[2] = (float)((w >> 16) & 0xFFu);
                mv[3] = (float)(w >> 24);
            }
            const float xs[4] = {X.x, X.y, X.z, X.w};
            const float ys[4] = {Y.x, Y.y, Y.z, Y.w};
            const float zs[4] = {Z.x, Z.y, Z.z, Z.w};
#pragma unroll
            for (int k = 0; k < 4; k++) {
                const float v0 = xs[k], v1 = ys[k], v2 = zs[k];
                float p0 = fmaf(Rp[0], v0, fmaf(Rp[1], v1, fmaf(Rp[2], v2, tp[0])));
                float p1 = fmaf(Rp[3], v0, fmaf(Rp[4], v1, fmaf(Rp[5], v2, tp[1])));
                float p2 = fmaf(Rp[6], v0, fmaf(Rp[7], v1, fmaf(Rp[8], v2, tp[2])));
                float g0 = fmaf(Rg[0], v0, fmaf(Rg[1], v1, fmaf(Rg[2], v2, tg[0])));
                float g1 = fmaf(Rg[3], v0, fmaf(Rg[4], v1, fmaf(Rg[5], v2, tg[1])));
                float g2 = fmaf(Rg[6], v0, fmaf(Rg[7], v1, fmaf(Rg[8], v2, tg[2])));
                float rp = frcp(p2);
                float rg = frcp(g2);
                float a0 = fmaf(p0, rp, -(g0 * rg));
                float a1 = fmaf(p1, rp, -(g1 * rg));
                float du = fx * a0;
                float dv = fy * a1;
                float d  = fsqrt(fmaf(du, du, dv * dv));
                sum = fmaf(d, mv[k], sum);
                cnt += mv[k];
            }
        }
        s1[tid] = sum; s2[tid] = cnt;
        __syncthreads();
        for (int s = 128; s > 0; s >>= 1) {
            if (tid < s) { s1[tid] += s1[tid + s]; s2[tid] += s2[tid + s]; }
            __syncthreads();
        }
        if (tid == 0) out[4 * NS + n] = s1[0] / fmaxf(s2[0], 1.0f);
    } else {
        // ---- ADD + PROJ over mesh points (+ RE/TE) ----
        const int obj = obj_id[n];
        const float* mp = mesh + (size_t)obj * MPTS * 3;
        float adsum = 0.f, pjsum = 0.f;

        for (int m = tid; m < MPTS; m += BLOCK) {
            const float v0 = __ldg(mp + m * 3 + 0);
            const float v1 = __ldg(mp + m * 3 + 1);
            const float v2 = __ldg(mp + m * 3 + 2);
            float p0 = fmaf(Rp[0], v0, fmaf(Rp[1], v1, fmaf(Rp[2], v2, tp[0])));
            float p1 = fmaf(Rp[3], v0, fmaf(Rp[4], v1, fmaf(Rp[5], v2, tp[1])));
            float p2 = fmaf(Rp[6], v0, fmaf(Rp[7], v1, fmaf(Rp[8], v2, tp[2])));
            float g0 = fmaf(Rg[0], v0, fmaf(Rg[1], v1, fmaf(Rg[2], v2, tg[0])));
            float g1 = fmaf(Rg[3], v0, fmaf(Rg[4], v1, fmaf(Rg[5], v2, tg[1])));
            float g2 = fmaf(Rg[6], v0, fmaf(Rg[7], v1, fmaf(Rg[8], v2, tg[2])));
            // ADD: |(pred - gt) transformed| == |xp - xg|
            float e0 = p0 - g0, e1 = p1 - g1, e2 = p2 - g2;
            adsum += fsqrt(fmaf(e0, e0, fmaf(e1, e1, e2 * e2)));
            // PROJ
            float rp = frcp(p2);
            float rg = frcp(g2);
            float a0 = fmaf(p0, rp, -(g0 * rg));
            float a1 = fmaf(p1, rp, -(g1 * rg));
            float du = fx * a0;
            float dv = fy * a1;
            pjsum += fsqrt(fmaf(du, du, dv * dv));
        }
        s1[tid] = adsum; s2[tid] = pjsum;
        __syncthreads();
        for (int s = 128; s > 0; s >>= 1) {
            if (tid < s) { s1[tid] += s1[tid + s]; s2[tid] += s2[tid + s]; }
            __syncthreads();
        }
        if (tid == 0) {
            const float invM = 1.0f / (float)MPTS;
            out[2 * NS + n] = (s1[0] * invM) / __ldg(diam + obj);
            out[3 * NS + n] = s2[0] * invM;
            float tr = 0.f;
#pragma unroll
            for (int i = 0; i < 9; i++) tr = fmaf(Rp[i], Rg[i], tr);
            tr = fminf(fmaxf(tr, -1.0f), 3.0f);
            out[n] = acosf((tr - 1.0f) * 0.5f) * 57.29577951308232f;
            const float d0 = tp[0] - tg[0], d1 = tp[1] - tg[1], d2 = tp[2] - tg[2];
            out[NS + n] = sqrtf(fmaf(d0, d0, fmaf(d1, d1, d2 * d2))) * 100.0f;
        }
    }
}

extern "C" void kernel_launch(void* const* d_in, const int* in_sizes, int n_in,
                              void* d_out, int out_size) {
    (void)in_sizes; (void)n_in; (void)out_size;
    const int*   obj_id = (const int*)  d_in[0];
    const float* camK   = (const float*)d_in[1];
    const float* gtR    = (const float*)d_in[2];
    const float* gtT    = (const float*)d_in[3];
    const float* prR    = (const float*)d_in[4];
    const float* prT    = (const float*)d_in[5];
    const float* coord  = (const float*)d_in[6];
    const void*  mask   =               d_in[7];
    const float* mesh   = (const float*)d_in[8];
    const float* diam   = (const float*)d_in[9];
    float* out = (float*)d_out;

    score_kernel<<<2 * NS, BLOCK>>>(obj_id, camK, gtR, gtT, prR, prT,
                                    coord, mask, mesh, diam, out);
}